// round 6
// baseline (speedup 1.0000x reference)
#include <cuda_runtime.h>

// ROIAlign / crop_and_resize (bilinear, extrapolation_value = 0)
// feature_map: [8, 64, 64, 256] f32 (B,H,W,C), rois: [8,128,4] f32
// out: [1024, 14, 14, 256] f32
//
// Persistent kernel: 592 blocks x 256 threads (8 warps). Each warp owns one
// 128-channel half (by warp parity) of a strided pixel stream and processes
// TWO pixels per iteration: all 8 gather LDG.128 issued before any consume
// (2x MLP vs one-pixel-per-warp), then 32 FMA + 2 streaming STG.128.

#define B 8
#define H 64
#define W 64
#define C 256
#define CROP 14
#define PIX_PER_ROI (CROP * CROP)          // 196
#define TOTAL_PIX (B * 128 * PIX_PER_ROI)  // 200704
#define NBLOCKS 592
#define WARPS_PER_BLOCK 8
#define GWARPS (NBLOCKS * WARPS_PER_BLOCK) // 4736
#define HALF_STREAMS (GWARPS / 2)          // 2368 pixel-streams per half

struct PxParams {
    const float* ptl;
    const float* ptr_;
    const float* pbl;
    const float* pbr;
    float wtl, wtr, wbl, wbr;
};

__device__ __forceinline__ PxParams px_setup(
    int pix, int coff, const float* __restrict__ fm, const float* __restrict__ rois)
{
    const int n   = pix / PIX_PER_ROI;
    const int rem = pix - n * PIX_PER_ROI;
    const int i   = rem / CROP;
    const int j   = rem - i * CROP;
    const int b   = n >> 7;

    const float4 r = __ldg((const float4*)(rois + n * 4));
    const float y1 = r.x, x1 = r.y, y2 = r.z, x2 = r.w;

    const float h_scale = (y2 - y1) * (float)(H - 1) / (float)(CROP - 1);
    const float w_scale = (x2 - x1) * (float)(W - 1) / (float)(CROP - 1);
    const float in_y = fmaf((float)i, h_scale, y1 * (float)(H - 1));
    const float in_x = fmaf((float)j, w_scale, x1 * (float)(W - 1));

    const bool valid = (in_y >= 0.f) && (in_y <= (float)(H - 1)) &&
                       (in_x >= 0.f) && (in_x <= (float)(W - 1));

    const float fy = floorf(in_y);
    const float fx = floorf(in_x);
    const float yl = in_y - fy;
    const float xl = in_x - fx;

    const int ty = min(max((int)fy, 0), H - 1);
    const int by = min(max((int)ceilf(in_y), 0), H - 1);
    const int lx = min(max((int)fx, 0), W - 1);
    const int rx = min(max((int)ceilf(in_x), 0), W - 1);

    PxParams p;
    p.wtl = (1.f - xl) * (1.f - yl);
    p.wtr = xl * (1.f - yl);
    p.wbl = (1.f - xl) * yl;
    p.wbr = xl * yl;
    if (!valid) { p.wtl = p.wtr = p.wbl = p.wbr = 0.f; }

    const size_t base = (size_t)b * (H * W * C);
    const float* rowT = fm + base + (size_t)ty * (W * C) + coff;
    const float* rowB = fm + base + (size_t)by * (W * C) + coff;
    p.ptl = rowT + lx * C;
    p.ptr_ = rowT + rx * C;
    p.pbl = rowB + lx * C;
    p.pbr = rowB + rx * C;
    return p;
}

__device__ __forceinline__ float4 px_lerp(
    const float4 tl, const float4 tr, const float4 bl, const float4 br,
    const PxParams& p)
{
    float4 o;
    o.x = fmaf(tl.x, p.wtl, fmaf(tr.x, p.wtr, fmaf(bl.x, p.wbl, br.x * p.wbr)));
    o.y = fmaf(tl.y, p.wtl, fmaf(tr.y, p.wtr, fmaf(bl.y, p.wbl, br.y * p.wbr)));
    o.z = fmaf(tl.z, p.wtl, fmaf(tr.z, p.wtr, fmaf(bl.z, p.wbl, br.z * p.wbr)));
    o.w = fmaf(tl.w, p.wtl, fmaf(tr.w, p.wtr, fmaf(bl.w, p.wbl, br.w * p.wbr)));
    return o;
}

__global__ __launch_bounds__(256) void roialign_kernel(
    const float* __restrict__ fm,
    const float* __restrict__ rois,
    float* __restrict__ out)
{
    const int lane  = threadIdx.x & 31;
    const int wid   = threadIdx.x >> 5;
    const int gwarp = blockIdx.x * WARPS_PER_BLOCK + wid;

    const int half = gwarp & 1;            // which 128-channel half
    const int ws   = gwarp >> 1;           // pixel-stream id, 0..2367
    const int coff = half * 128 + lane * 4;

    for (int p0 = ws; p0 < TOTAL_PIX; p0 += 2 * HALF_STREAMS) {
        const int  p1   = p0 + HALF_STREAMS;
        const bool has1 = (p1 < TOTAL_PIX);
        const int  q1   = has1 ? p1 : p0;      // safe addresses when no p1

        const PxParams a = px_setup(p0, coff, fm, rois);
        const PxParams b = px_setup(q1, coff, fm, rois);

        // Issue all 8 gathers before any consume (2 pixels' worth of MLP)
        const float4 atl = __ldg((const float4*)a.ptl);
        const float4 atr = __ldg((const float4*)a.ptr_);
        const float4 abl = __ldg((const float4*)a.pbl);
        const float4 abr = __ldg((const float4*)a.pbr);
        const float4 btl = __ldg((const float4*)b.ptl);
        const float4 btr = __ldg((const float4*)b.ptr_);
        const float4 bbl = __ldg((const float4*)b.pbl);
        const float4 bbr = __ldg((const float4*)b.pbr);

        const float4 o0 = px_lerp(atl, atr, abl, abr, a);
        __stcs((float4*)(out + (size_t)p0 * C + coff), o0);

        if (has1) {
            const float4 o1 = px_lerp(btl, btr, bbl, bbr, b);
            __stcs((float4*)(out + (size_t)p1 * C + coff), o1);
        }
    }
}

extern "C" void kernel_launch(void* const* d_in, const int* in_sizes, int n_in,
                              void* d_out, int out_size)
{
    const float* fm   = (const float*)d_in[0];
    const float* rois = (const float*)d_in[1];
    float* out = (float*)d_out;

    roialign_kernel<<<NBLOCKS, 256>>>(fm, rois, out);
}

// round 7
// speedup vs baseline: 1.1393x; 1.1393x over previous
#include <cuda_runtime.h>

// ROIAlign / crop_and_resize (bilinear, extrapolation_value = 0)
// feature_map: [8, 64, 64, 256] f32 (B,H,W,C), rois: [8,128,4] f32
// out: [1024, 14, 14, 256] f32
//
// R3 structure (best known): one warp per output pixel, lane covers channels
// [lane*4, lane*4+4) and [128+lane*4, ...): 8 independent gather LDG.128 per
// thread, then 2 write-through STG.128 (__stwt) so the 205MB output stream
// never allocates/dirties L2 — keeps the 33MB feature map L2-resident.

#define B 8
#define H 64
#define W 64
#define C 256
#define NUM_ROIS 128
#define CROP 14
#define PIX_PER_ROI (CROP * CROP)          // 196
#define TOTAL_PIX (B * NUM_ROIS * PIX_PER_ROI)  // 200704
#define WARPS_PER_BLOCK 8

__global__ __launch_bounds__(256) void roialign_kernel(
    const float* __restrict__ fm,
    const float* __restrict__ rois,
    float* __restrict__ out)
{
    const int lane = threadIdx.x & 31;
    const int wid  = threadIdx.x >> 5;
    const int pix  = blockIdx.x * WARPS_PER_BLOCK + wid;

    // Decompose pixel id (warp-uniform values)
    const int n   = pix / PIX_PER_ROI;
    const int rem = pix - n * PIX_PER_ROI;
    const int i   = rem / CROP;
    const int j   = rem - i * CROP;
    const int b   = n >> 7;

    // ROI coords: all 32 lanes load same 16B (broadcast)
    const float4 r = __ldg((const float4*)(rois + n * 4));
    const float y1 = r.x, x1 = r.y, y2 = r.z, x2 = r.w;

    const float h_scale = (y2 - y1) * (float)(H - 1) / (float)(CROP - 1);
    const float w_scale = (x2 - x1) * (float)(W - 1) / (float)(CROP - 1);
    const float in_y = fmaf((float)i, h_scale, y1 * (float)(H - 1));
    const float in_x = fmaf((float)j, w_scale, x1 * (float)(W - 1));

    const bool valid = (in_y >= 0.f) && (in_y <= (float)(H - 1)) &&
                       (in_x >= 0.f) && (in_x <= (float)(W - 1));

    const float fy = floorf(in_y);
    const float fx = floorf(in_x);
    const float yl = in_y - fy;
    const float xl = in_x - fx;

    int ty = min(max((int)fy, 0), H - 1);
    int by = min(max((int)ceilf(in_y), 0), H - 1);
    int lx = min(max((int)fx, 0), W - 1);
    int rx = min(max((int)ceilf(in_x), 0), W - 1);

    // Bilinear weights; zeroed when invalid (output becomes exact 0)
    float wtl = (1.f - xl) * (1.f - yl);
    float wtr = xl * (1.f - yl);
    float wbl = (1.f - xl) * yl;
    float wbr = xl * yl;
    if (!valid) { wtl = wtr = wbl = wbr = 0.f; ty = by = lx = rx = 0; }

    const size_t base = (size_t)b * (H * W * C);
    const float* ptl = fm + base + (size_t)(ty * W + lx) * C + lane * 4;
    const float* ptr_ = fm + base + (size_t)(ty * W + rx) * C + lane * 4;
    const float* pbl = fm + base + (size_t)(by * W + lx) * C + lane * 4;
    const float* pbr = fm + base + (size_t)(by * W + rx) * C + lane * 4;

    // 8 independent gathers (two 128-channel halves), all issued up front
    const float4 tl0 = __ldg((const float4*)(ptl));
    const float4 tr0 = __ldg((const float4*)(ptr_));
    const float4 bl0 = __ldg((const float4*)(pbl));
    const float4 br0 = __ldg((const float4*)(pbr));
    const float4 tl1 = __ldg((const float4*)(ptl + 128));
    const float4 tr1 = __ldg((const float4*)(ptr_ + 128));
    const float4 bl1 = __ldg((const float4*)(pbl + 128));
    const float4 br1 = __ldg((const float4*)(pbr + 128));

    float4 o0, o1;
    o0.x = fmaf(tl0.x, wtl, fmaf(tr0.x, wtr, fmaf(bl0.x, wbl, br0.x * wbr)));
    o0.y = fmaf(tl0.y, wtl, fmaf(tr0.y, wtr, fmaf(bl0.y, wbl, br0.y * wbr)));
    o0.z = fmaf(tl0.z, wtl, fmaf(tr0.z, wtr, fmaf(bl0.z, wbl, br0.z * wbr)));
    o0.w = fmaf(tl0.w, wtl, fmaf(tr0.w, wtr, fmaf(bl0.w, wbl, br0.w * wbr)));
    o1.x = fmaf(tl1.x, wtl, fmaf(tr1.x, wtr, fmaf(bl1.x, wbl, br1.x * wbr)));
    o1.y = fmaf(tl1.y, wtl, fmaf(tr1.y, wtr, fmaf(bl1.y, wbl, br1.y * wbr)));
    o1.z = fmaf(tl1.z, wtl, fmaf(tr1.z, wtr, fmaf(bl1.z, wbl, br1.z * wbr)));
    o1.w = fmaf(tl1.w, wtl, fmaf(tr1.w, wtr, fmaf(bl1.w, wbl, br1.w * wbr)));

    // Write-through streaming stores: don't allocate/dirty L2 with output
    float* op = out + (size_t)pix * C + lane * 4;
    __stwt((float4*)op, o0);
    __stwt((float4*)(op + 128), o1);
}

extern "C" void kernel_launch(void* const* d_in, const int* in_sizes, int n_in,
                              void* d_out, int out_size)
{
    const float* fm   = (const float*)d_in[0];
    const float* rois = (const float*)d_in[1];
    float* out = (float*)d_out;

    roialign_kernel<<<TOTAL_PIX / WARPS_PER_BLOCK, 256>>>(fm, rois, out);
}

// round 8
// speedup vs baseline: 1.2622x; 1.1079x over previous
#include <cuda_runtime.h>

// ROIAlign / crop_and_resize (bilinear, extrapolation_value = 0)
// feature_map: [8, 64, 64, 256] f32 (B,H,W,C), rois: [8,128,4] f32
// out: [1024, 14, 14, 256] f32
//
// Best-known structure (R3): one warp per output pixel; lane covers channels
// [lane*4, lane*4+4) and [128+lane*4, ...): 8 independent gather LDG.128 per
// thread issued before any consume, then 2 streaming STG.128 (__stcs).
// This round: pure 32-bit byte-offset addressing (fm 33.5MB, out 205MB both
// < 2^31) to cut IMAD.WIDE pairs + registers, and no bounds guard.

#define B 8
#define H 64
#define W 64
#define C 256
#define NUM_ROIS 128
#define CROP 14
#define PIX_PER_ROI (CROP * CROP)               // 196
#define TOTAL_PIX (B * NUM_ROIS * PIX_PER_ROI)  // 200704
#define WARPS_PER_BLOCK 8

__global__ __launch_bounds__(256) void roialign_kernel(
    const float* __restrict__ fm,
    const float* __restrict__ rois,
    float* __restrict__ out)
{
    const int lane = threadIdx.x & 31;
    const int wid  = threadIdx.x >> 5;
    const int pix  = blockIdx.x * WARPS_PER_BLOCK + wid;   // grid divides exactly

    // Decompose pixel id (warp-uniform)
    const int n   = pix / PIX_PER_ROI;
    const int rem = pix - n * PIX_PER_ROI;
    const int i   = rem / CROP;
    const int j   = rem - i * CROP;
    const int b   = n >> 7;

    // ROI coords: warp-broadcast 16B load
    const float4 r = __ldg((const float4*)(rois + n * 4));
    const float y1 = r.x, x1 = r.y, y2 = r.z, x2 = r.w;

    const float h_scale = (y2 - y1) * (float)(H - 1) / (float)(CROP - 1);
    const float w_scale = (x2 - x1) * (float)(W - 1) / (float)(CROP - 1);
    const float in_y = fmaf((float)i, h_scale, y1 * (float)(H - 1));
    const float in_x = fmaf((float)j, w_scale, x1 * (float)(W - 1));

    const bool valid = (in_y >= 0.f) && (in_y <= (float)(H - 1)) &&
                       (in_x >= 0.f) && (in_x <= (float)(W - 1));

    const float fy = floorf(in_y);
    const float fx = floorf(in_x);
    const float yl = in_y - fy;
    const float xl = in_x - fx;

    int ty = min(max((int)fy, 0), H - 1);
    int by = min(max((int)ceilf(in_y), 0), H - 1);
    int lx = min(max((int)fx, 0), W - 1);
    int rx = min(max((int)ceilf(in_x), 0), W - 1);

    // Bilinear weights; zeroed when invalid (output becomes exact 0)
    float wtl = (1.f - xl) * (1.f - yl);
    float wtr = xl * (1.f - yl);
    float wbl = (1.f - xl) * yl;
    float wbr = xl * yl;
    if (!valid) { wtl = wtr = wbl = wbr = 0.f; ty = by = lx = rx = 0; }

    // 32-bit byte offsets: fm is 33.5MB, out is 205MB — both fit in int
    const char* fmb = (const char*)fm;
    const int cb   = lane * 16;                       // per-lane channel bytes
    const int base = b * (H * W * C * 4);
    const int oT   = base + ty * (W * C * 4) + cb;
    const int oB   = base + by * (W * C * 4) + cb;
    const int oL   = lx * (C * 4);
    const int oR   = rx * (C * 4);

    // 8 independent gathers (two 128-channel halves), all issued up front
    const float4 tl0 = __ldg((const float4*)(fmb + oT + oL));
    const float4 tr0 = __ldg((const float4*)(fmb + oT + oR));
    const float4 bl0 = __ldg((const float4*)(fmb + oB + oL));
    const float4 br0 = __ldg((const float4*)(fmb + oB + oR));
    const float4 tl1 = __ldg((const float4*)(fmb + oT + oL + 512));
    const float4 tr1 = __ldg((const float4*)(fmb + oT + oR + 512));
    const float4 bl1 = __ldg((const float4*)(fmb + oB + oL + 512));
    const float4 br1 = __ldg((const float4*)(fmb + oB + oR + 512));

    char* ob = (char*)out + pix * (C * 4) + cb;

    float4 o0;
    o0.x = fmaf(tl0.x, wtl, fmaf(tr0.x, wtr, fmaf(bl0.x, wbl, br0.x * wbr)));
    o0.y = fmaf(tl0.y, wtl, fmaf(tr0.y, wtr, fmaf(bl0.y, wbl, br0.y * wbr)));
    o0.z = fmaf(tl0.z, wtl, fmaf(tr0.z, wtr, fmaf(bl0.z, wbl, br0.z * wbr)));
    o0.w = fmaf(tl0.w, wtl, fmaf(tr0.w, wtr, fmaf(bl0.w, wbl, br0.w * wbr)));
    __stcs((float4*)ob, o0);

    float4 o1;
    o1.x = fmaf(tl1.x, wtl, fmaf(tr1.x, wtr, fmaf(bl1.x, wbl, br1.x * wbr)));
    o1.y = fmaf(tl1.y, wtl, fmaf(tr1.y, wtr, fmaf(bl1.y, wbl, br1.y * wbr)));
    o1.z = fmaf(tl1.z, wtl, fmaf(tr1.z, wtr, fmaf(bl1.z, wbl, br1.z * wbr)));
    o1.w = fmaf(tl1.w, wtl, fmaf(tr1.w, wtr, fmaf(bl1.w, wbl, br1.w * wbr)));
    __stcs((float4*)(ob + 512), o1);
}

extern "C" void kernel_launch(void* const* d_in, const int* in_sizes, int n_in,
                              void* d_out, int out_size)
{
    const float* fm   = (const float*)d_in[0];
    const float* rois = (const float*)d_in[1];
    float* out = (float*)d_out;

    roialign_kernel<<<TOTAL_PIX / WARPS_PER_BLOCK, 256>>>(fm, rois, out);
}